// round 1
// baseline (speedup 1.0000x reference)
#include <cuda_runtime.h>

#define NN 20000
#define NE 320000
#define FF 64
#define RR 8
#define SS 10
#define HH 64
#define PP 5

#define INV_SQRT3 0.5773502691896258f
#define INV_SQRT2 0.7071067811865476f

// scratch (static __device__ — no allocations allowed)
__device__ float g_s1[NN * FF];
__device__ float g_v1[NN * FF * 3];
__device__ float g_As[NN * FF];
__device__ float g_Av[NN * FF * 3];

// ---------------------------------------------------------------------------
// Kernel A: s1 = s @ W_lin_s ; v1 = einsum(v, W_lin_v). Also zero A_s/A_v.
// block = 256 threads = 4 nodes x 64 output channels
// ---------------------------------------------------------------------------
__global__ __launch_bounds__(256) void knodeA(
    const float* __restrict__ s, const float* __restrict__ v,
    const float* __restrict__ Wls, const float* __restrict__ Wlv)
{
    __shared__ float sWls[FF * FF], sWlv[FF * FF];
    __shared__ float sS[4 * FF], sV[4 * FF * 3];
    for (int i = threadIdx.x; i < FF * FF; i += blockDim.x) {
        sWls[i] = Wls[i];
        sWlv[i] = Wlv[i];
    }
    const int ngrp = NN / 4;
    for (int grp = blockIdx.x; grp < ngrp; grp += gridDim.x) {
        __syncthreads();
        int nbase = grp * 4;
        for (int i = threadIdx.x; i < 4 * FF; i += blockDim.x)
            sS[i] = s[nbase * FF + i];
        for (int i = threadIdx.x; i < 4 * FF * 3; i += blockDim.x)
            sV[i] = v[nbase * FF * 3 + i];
        __syncthreads();
        int nl = threadIdx.x >> 6, g = threadIdx.x & 63;
        int n = nbase + nl;
        const float* ps = sS + nl * FF;
        const float* pv = sV + nl * FF * 3;
        float as = 0.f, ax = 0.f, ay = 0.f, az = 0.f;
#pragma unroll 8
        for (int f = 0; f < FF; f++) {
            float wls = sWls[f * FF + g], wlv = sWlv[f * FF + g];
            as += ps[f] * wls;
            ax += pv[f * 3 + 0] * wlv;
            ay += pv[f * 3 + 1] * wlv;
            az += pv[f * 3 + 2] * wlv;
        }
        g_s1[n * FF + g] = as;
        g_v1[n * FF * 3 + g * 3 + 0] = ax;
        g_v1[n * FF * 3 + g * 3 + 1] = ay;
        g_v1[n * FF * 3 + g * 3 + 2] = az;
        g_As[n * FF + g] = 0.f;
        g_Av[n * FF * 3 + g * 3 + 0] = 0.f;
        g_Av[n * FF * 3 + g * 3 + 1] = 0.f;
        g_Av[n * FF * 3 + g * 3 + 2] = 0.f;
    }
}

// ---------------------------------------------------------------------------
// Kernel B: per-edge radial MLP + CG tensor product + atomic scatter.
// thread-per-edge; h[64] in registers; W_rad2 transposed in smem [col][j]
// so all lanes broadcast-read the same W address (LDS.128 broadcast).
// dynamic smem: Wt 320*64 floats + W1t 64*8 floats = 83968 bytes
// ---------------------------------------------------------------------------
__global__ __launch_bounds__(256, 2) void kedge(
    const float* __restrict__ Y1, const float* __restrict__ efg,
    const int* __restrict__ senders, const int* __restrict__ receivers,
    const float* __restrict__ W_rad1, const float* __restrict__ W_rad2)
{
    extern __shared__ float smem[];
    float* sWt = smem;                 // [320][64]: sWt[col*64+j] = W_rad2[j*320+col]
    float* sW1 = smem + PP * FF * HH;  // [64][8] : sW1[j*8+r]   = W_rad1[r*64+j]

    for (int i = threadIdx.x; i < HH * PP * FF; i += blockDim.x) {
        int j = i / (PP * FF);
        int col = i % (PP * FF);
        sWt[col * HH + j] = W_rad2[i];
    }
    for (int i = threadIdx.x; i < RR * HH; i += blockDim.x) {
        int r = i / HH, j = i % HH;
        sW1[j * RR + r] = W_rad1[i];
    }
    __syncthreads();

    int stride = gridDim.x * blockDim.x;
    for (int e = blockIdx.x * blockDim.x + threadIdx.x; e < NE; e += stride) {
        // radial basis -> hidden h (silu), h kept in registers
        float4 ef0 = *(const float4*)(efg + e * RR);
        float4 ef1 = *(const float4*)(efg + e * RR + 4);
        float h[HH];
#pragma unroll
        for (int j = 0; j < HH; j++) {
            const float4* w = (const float4*)(sW1 + j * RR);
            float4 wa = w[0], wb = w[1];
            float x = ef0.x * wa.x + ef0.y * wa.y + ef0.z * wa.z + ef0.w * wa.w +
                      ef1.x * wb.x + ef1.y * wb.y + ef1.z * wb.z + ef1.w * wb.w;
            h[j] = __fdividef(x, 1.f + __expf(-x));  // silu
        }

        int snd = senders[e];
        int rcv = receivers[e];
        float Yx = Y1[e * 3 + 0], Yy = Y1[e * 3 + 1], Yz = Y1[e * 3 + 2];
        const float* s1p = g_s1 + snd * FF;
        const float* v1p = g_v1 + snd * FF * 3;
        float* Asp = g_As + rcv * FF;
        float* Avp = g_Av + rcv * FF * 3;

        for (int f = 0; f < FF; f++) {
            // tw[p] = sum_j h[j] * W_rad2[j, p*64+f]
            float tw[PP];
#pragma unroll
            for (int p = 0; p < PP; p++) {
                const float4* wp = (const float4*)(sWt + (p * FF + f) * HH);
                float acc = 0.f;
#pragma unroll
                for (int j4 = 0; j4 < HH / 4; j4++) {
                    float4 w = wp[j4];
                    acc += h[4 * j4 + 0] * w.x + h[4 * j4 + 1] * w.y +
                           h[4 * j4 + 2] * w.z + h[4 * j4 + 3] * w.w;
                }
                tw[p] = acc;
            }
            float ssf = __ldg(s1p + f);
            float vx = __ldg(v1p + f * 3 + 0);
            float vy = __ldg(v1p + f * 3 + 1);
            float vz = __ldg(v1p + f * 3 + 2);
            float dotf = vx * Yx + vy * Yy + vz * Yz;
            float cx = vy * Yz - vz * Yy;
            float cy = vz * Yx - vx * Yz;
            float cz = vx * Yy - vy * Yx;
            float ms = tw[0] * ssf + tw[1] * dotf * INV_SQRT3;
            float t2s = tw[2] * ssf;
            float t4 = tw[4] * INV_SQRT2;
            atomicAdd(Asp + f, ms);
            atomicAdd(Avp + f * 3 + 0, t2s * Yx + tw[3] * vx + t4 * cx);
            atomicAdd(Avp + f * 3 + 1, t2s * Yy + tw[3] * vy + t4 * cy);
            atomicAdd(Avp + f * 3 + 2, t2s * Yz + tw[3] * vz + t4 * cz);
        }
    }
}

// ---------------------------------------------------------------------------
// Kernel C: node post: W_int + species skip + product basis + W_prod + readout
// block = 256 = 4 nodes x 64 channels; grid-stride over node groups
// ---------------------------------------------------------------------------
__global__ __launch_bounds__(256, 2) void knodeC(
    const float* __restrict__ s, const float* __restrict__ v,
    const int* __restrict__ spec,
    const float* __restrict__ W_sc_s, const float* __restrict__ W_sc_v,
    const float* __restrict__ W_int_s, const float* __restrict__ W_int_v,
    const float* __restrict__ w_prod_s, const float* __restrict__ w_prod_v,
    const float* __restrict__ W_prod_s, const float* __restrict__ W_prod_v,
    const float* __restrict__ W_read,
    float* __restrict__ out_node, float* __restrict__ out_s,
    float* __restrict__ out_v)
{
    extern __shared__ float sm[];
    float* sWis = sm;                 // 4096
    float* sWiv = sWis + FF * FF;     // 4096
    float* sWps = sWiv + FF * FF;     // 4096
    float* sWpv = sWps + FF * FF;     // 4096
    float* sWr  = sWpv + FF * FF;     // 64
    float* sAs  = sWr + FF;           // 256
    float* sAv  = sAs + 4 * FF;       // 768
    float* sSin = sAv + 4 * FF * 3;   // 256
    float* sVin = sSin + 4 * FF;      // 768
    float* sBs  = sVin + 4 * FF * 3;  // 256
    float* sBv  = sBs + 4 * FF;       // 768
    float* sRed = sBv + 4 * FF * 3;   // 8
    __shared__ int sSpec[4];

    for (int i = threadIdx.x; i < FF * FF; i += blockDim.x) {
        sWis[i] = W_int_s[i];
        sWiv[i] = W_int_v[i];
        sWps[i] = W_prod_s[i];
        sWpv[i] = W_prod_v[i];
    }
    if (threadIdx.x < FF) sWr[threadIdx.x] = W_read[threadIdx.x];

    const int ngrp = NN / 4;
    for (int grp = blockIdx.x; grp < ngrp; grp += gridDim.x) {
        __syncthreads();
        int nbase = grp * 4;
        for (int i = threadIdx.x; i < 4 * FF; i += blockDim.x) {
            sAs[i] = g_As[nbase * FF + i];
            sSin[i] = s[nbase * FF + i];
        }
        for (int i = threadIdx.x; i < 4 * FF * 3; i += blockDim.x) {
            sAv[i] = g_Av[nbase * FF * 3 + i];
            sVin[i] = v[nbase * FF * 3 + i];
        }
        if (threadIdx.x < 4) sSpec[threadIdx.x] = spec[nbase + threadIdx.x];
        __syncthreads();

        int nl = threadIdx.x >> 6, g = threadIdx.x & 63;
        int n = nbase + nl;
        int sp = sSpec[nl];
        const float* Wscs = W_sc_s + sp * FF * FF;
        const float* Wscv = W_sc_v + sp * FF * FF;
        const float* pAs = sAs + nl * FF;
        const float* pAv = sAv + nl * FF * 3;
        const float* pS = sSin + nl * FF;
        const float* pV = sVin + nl * FF * 3;

        float as = 0.f, avx = 0.f, avy = 0.f, avz = 0.f;
        float scs = 0.f, scvx = 0.f, scvy = 0.f, scvz = 0.f;
#pragma unroll 4
        for (int f = 0; f < FF; f++) {
            float wis = sWis[f * FF + g], wiv = sWiv[f * FF + g];
            float wss = __ldg(Wscs + f * FF + g);
            float wsv = __ldg(Wscv + f * FF + g);
            as += pAs[f] * wis;
            avx += pAv[f * 3 + 0] * wiv;
            avy += pAv[f * 3 + 1] * wiv;
            avz += pAv[f * 3 + 2] * wiv;
            scs += pS[f] * wss;
            scvx += pV[f * 3 + 0] * wsv;
            scvy += pV[f * 3 + 1] * wsv;
            scvz += pV[f * 3 + 2] * wsv;
        }
        const float inv = 0.25f;  // 1/sqrt(16)
        as *= inv; avx *= inv; avy *= inv; avz *= inv;

        const float* wps = w_prod_s + sp * 5 * FF;
        const float* wpv = w_prod_v + sp * 4 * FF;
        float d = avx * avx + avy * avy + avz * avz;
        float as2 = as * as;
        float Bs = wps[0 * FF + g] * as + wps[1 * FF + g] * as2 +
                   wps[2 * FF + g] * d + wps[3 * FF + g] * as2 * as +
                   wps[4 * FF + g] * as * d;
        float gv = wpv[0 * FF + g] + wpv[1 * FF + g] * as +
                   wpv[2 * FF + g] * as2 + wpv[3 * FF + g] * d;
        sBs[nl * FF + g] = Bs;
        sBv[nl * FF * 3 + g * 3 + 0] = gv * avx;
        sBv[nl * FF * 3 + g * 3 + 1] = gv * avy;
        sBv[nl * FF * 3 + g * 3 + 2] = gv * avz;
        __syncthreads();

        const float* pBs = sBs + nl * FF;
        const float* pBv = sBv + nl * FF * 3;
        float so = scs, vox = scvx, voy = scvy, voz = scvz;
#pragma unroll 4
        for (int f = 0; f < FF; f++) {
            float wp = sWps[f * FF + g], wv = sWpv[f * FF + g];
            so += pBs[f] * wp;
            vox += pBv[f * 3 + 0] * wv;
            voy += pBv[f * 3 + 1] * wv;
            voz += pBv[f * 3 + 2] * wv;
        }
        out_s[n * FF + g] = so;
        out_v[n * FF * 3 + g * 3 + 0] = vox;
        out_v[n * FF * 3 + g * 3 + 1] = voy;
        out_v[n * FF * 3 + g * 3 + 2] = voz;

        // readout: node_out[n] = sum_g so * W_read[g]
        float r = so * sWr[g];
#pragma unroll
        for (int o = 16; o > 0; o >>= 1) r += __shfl_down_sync(0xffffffffu, r, o);
        if ((threadIdx.x & 31) == 0) sRed[threadIdx.x >> 5] = r;
        __syncthreads();
        if ((threadIdx.x & 63) == 0)
            out_node[n] = sRed[threadIdx.x >> 5] + sRed[(threadIdx.x >> 5) + 1];
    }
}

// ---------------------------------------------------------------------------
extern "C" void kernel_launch(void* const* d_in, const int* in_sizes, int n_in,
                              void* d_out, int out_size)
{
    const float* s    = (const float*)d_in[0];
    const float* v    = (const float*)d_in[1];
    const float* Y1   = (const float*)d_in[2];
    const float* ef   = (const float*)d_in[3];
    const int*   spec = (const int*)d_in[4];
    const int*   snd  = (const int*)d_in[5];
    const int*   rcv  = (const int*)d_in[6];
    const float* Wls  = (const float*)d_in[7];
    const float* Wlv  = (const float*)d_in[8];
    const float* Wscs = (const float*)d_in[9];
    const float* Wscv = (const float*)d_in[10];
    const float* Wr1  = (const float*)d_in[11];
    const float* Wr2  = (const float*)d_in[12];
    const float* Wis  = (const float*)d_in[13];
    const float* Wiv  = (const float*)d_in[14];
    const float* wps  = (const float*)d_in[15];
    const float* wpv  = (const float*)d_in[16];
    const float* Wps  = (const float*)d_in[17];
    const float* Wpv  = (const float*)d_in[18];
    const float* Wrd  = (const float*)d_in[19];

    float* out = (float*)d_out;
    float* out_node = out;
    float* out_s = out + NN;
    float* out_v = out + NN + NN * FF;

    const int smemB = (PP * FF * HH + RR * HH) * (int)sizeof(float);   // 83968
    const int smemC = (4 * FF * FF + FF + 4 * FF * 2 + 4 * FF * 3 * 2 +
                       4 * FF + 4 * FF * 3 + 8) * (int)sizeof(float);  // ~78KB
    cudaFuncSetAttribute(kedge, cudaFuncAttributeMaxDynamicSharedMemorySize, smemB);
    cudaFuncSetAttribute(knodeC, cudaFuncAttributeMaxDynamicSharedMemorySize, smemC);

    knodeA<<<592, 256>>>(s, v, Wls, Wlv);
    kedge<<<296, 256, smemB>>>(Y1, ef, snd, rcv, Wr1, Wr2);
    knodeC<<<296, 256, smemC>>>(s, v, spec, Wscs, Wscv, Wis, Wiv,
                                wps, wpv, Wps, Wpv, Wrd,
                                out_node, out_s, out_v);
}

// round 2
// speedup vs baseline: 1.9733x; 1.9733x over previous
#include <cuda_runtime.h>

#define NN 20000
#define NE 320000
#define FF 64
#define RR 8
#define HH 64
#define PP 5
#define TILE_E 32
#define NTILE (NE / TILE_E)

#define INV_SQRT3 0.5773502691896258f
#define INV_SQRT2 0.7071067811865476f

typedef unsigned long long u64;

// scratch (static __device__ — no allocations allowed)
__device__ float g_s1[NN * FF];
__device__ float g_v1[NN * FF * 3];
__device__ float g_As[NN * FF];
__device__ float g_Av[NN * FF * 3];

__device__ __forceinline__ u64 pack2(float lo, float hi) {
    u64 r; asm("mov.b64 %0, {%1,%2};" : "=l"(r) : "f"(lo), "f"(hi)); return r;
}
__device__ __forceinline__ void ffma2(u64& d, u64 a, u64 b) {
    asm("fma.rn.f32x2 %0, %1, %2, %0;" : "+l"(d) : "l"(a), "l"(b));
}
__device__ __forceinline__ float2 unpk(u64 v) {
    float lo, hi; asm("mov.b64 {%0,%1}, %2;" : "=f"(lo), "=f"(hi) : "l"(v));
    return make_float2(lo, hi);
}
__device__ __forceinline__ void red4(float* addr, float a, float b, float c, float d) {
    asm volatile("red.global.add.v4.f32 [%0], {%1,%2,%3,%4};"
                 :: "l"(__cvta_generic_to_global(addr)),
                    "f"(a), "f"(b), "f"(c), "f"(d) : "memory");
}

// ---------------------------------------------------------------------------
// Kernel A: s1 = s @ W_lin_s ; v1 = einsum(v, W_lin_v). Zero A_s/A_v.
// float2-packed weights, float4-packed v in smem, smem-staged coalesced stores.
// ---------------------------------------------------------------------------
__global__ __launch_bounds__(256) void knodeA(
    const float* __restrict__ s, const float* __restrict__ v,
    const float* __restrict__ Wls, const float* __restrict__ Wlv)
{
    __shared__ float2 sW[FF * FF];     // {wls, wlv} 32KB
    __shared__ float sS[4 * FF];
    __shared__ float4 sV[4 * FF];      // (x,y,z,pad)
    __shared__ float sVo[4 * FF * 3];  // staged v1 output

    for (int i = threadIdx.x; i < FF * FF; i += blockDim.x)
        sW[i] = make_float2(Wls[i], Wlv[i]);

    const int ngrp = NN / 4;
    for (int grp = blockIdx.x; grp < ngrp; grp += gridDim.x) {
        __syncthreads();
        int nbase = grp * 4;
        for (int i = threadIdx.x; i < 4 * FF; i += blockDim.x)
            sS[i] = s[nbase * FF + i];
        float* sVf = (float*)sV;
        for (int i = threadIdx.x; i < 4 * FF * 3; i += blockDim.x)
            sVf[(i / 3) * 4 + (i % 3)] = v[nbase * FF * 3 + i];
        __syncthreads();

        int nl = threadIdx.x >> 6, g = threadIdx.x & 63;
        int n = nbase + nl;
        const float* ps = sS + nl * FF;
        const float4* pv = sV + nl * FF;
        float as = 0.f, ax = 0.f, ay = 0.f, az = 0.f;
#pragma unroll 8
        for (int f = 0; f < FF; f++) {
            float2 w = sW[f * FF + g];
            float4 vv = pv[f];
            as += ps[f] * w.x;
            ax += vv.x * w.y;
            ay += vv.y * w.y;
            az += vv.z * w.y;
        }
        g_s1[n * FF + g] = as;
        sVo[nl * FF * 3 + g * 3 + 0] = ax;
        sVo[nl * FF * 3 + g * 3 + 1] = ay;
        sVo[nl * FF * 3 + g * 3 + 2] = az;
        __syncthreads();
        for (int i = threadIdx.x; i < 4 * FF * 3; i += blockDim.x) {
            g_v1[nbase * FF * 3 + i] = sVo[i];
            g_Av[nbase * FF * 3 + i] = 0.f;
        }
        for (int i = threadIdx.x; i < 4 * FF; i += blockDim.x)
            g_As[nbase * FF + i] = 0.f;
    }
}

// ---------------------------------------------------------------------------
// Kernel B (edge): tiled register-blocked GEMM (FFMA2) + TP + vector scatter.
// Tile = 32 edges. 256 threads: eg = tid&15 (2 edges each), fg = tid>>4 (4 f).
// smem: W2 [64][320] (80KB) + W1t [64][8] + h [64][32] + edge meta = ~92.8KB.
// ---------------------------------------------------------------------------
__global__ __launch_bounds__(256, 2) void kedge(
    const float* __restrict__ Y1, const float* __restrict__ efg,
    const int* __restrict__ senders, const int* __restrict__ receivers,
    const float* __restrict__ W_rad1, const float* __restrict__ W_rad2)
{
    extern __shared__ float smem[];
    float* sW2 = smem;                       // 20480 floats: [j][320]
    float* sW1 = sW2 + HH * PP * FF;         // 512: [j][8] transposed
    float* sh  = sW1 + 512;                  // 2048: [j][32]
    float* sY  = sh + HH * TILE_E;           // 96
    int* sSnd  = (int*)(sY + 96);            // 32
    int* sRcv  = sSnd + TILE_E;              // 32

    const int tid = threadIdx.x;
    for (int i = tid; i < HH * PP * FF; i += 256)
        sW2[i] = W_rad2[i];
    for (int i = tid; i < RR * HH; i += 256) {
        int r = i / HH, j = i % HH;
        sW1[j * RR + r] = W_rad1[i];
    }

    const int lane_e = tid & 31;   // edge slot for phase A
    const int oct = tid >> 5;      // j-octave for phase A
    const int eg = tid & 15;       // edge-group (2 edges) for GEMM
    const int fg = tid >> 4;       // f-group (4 channels)

    for (int tile = blockIdx.x; tile < NTILE; tile += gridDim.x) {
        __syncthreads();
        // ---- edge meta ----
        if (tid < TILE_E) {
            sSnd[tid] = senders[tile * TILE_E + tid];
            sRcv[tid] = receivers[tile * TILE_E + tid];
        }
        if (tid >= 128 && tid < 128 + 3 * TILE_E)
            sY[tid - 128] = Y1[tile * 3 * TILE_E + (tid - 128)];

        // ---- phase A: h = silu(ef @ W1), each thread 8 j-values ----
        {
            int e = tile * TILE_E + lane_e;
            float4 ef0 = *(const float4*)(efg + e * RR);
            float4 ef1 = *(const float4*)(efg + e * RR + 4);
#pragma unroll
            for (int jj = 0; jj < 8; jj++) {
                int j = oct * 8 + jj;
                const float4* w = (const float4*)(sW1 + j * RR);
                float4 wa = w[0], wb = w[1];
                float x = ef0.x * wa.x + ef0.y * wa.y + ef0.z * wa.z + ef0.w * wa.w +
                          ef1.x * wb.x + ef1.y * wb.y + ef1.z * wb.z + ef1.w * wb.w;
                sh[j * TILE_E + lane_e] = __fdividef(x, 1.f + __expf(-x));
            }
        }
        __syncthreads();

        // ---- phase B: tw = h @ W2, FFMA2 register-blocked ----
        u64 acc[2][5][2];
#pragma unroll
        for (int a = 0; a < 2; a++)
#pragma unroll
            for (int p = 0; p < 5; p++) {
                acc[a][p][0] = 0ull; acc[a][p][1] = 0ull;
            }
        {
            const float* hrow = sh + eg * 2;
            const float* wrow = sW2 + fg * 4;
#pragma unroll 4
            for (int j = 0; j < HH; j++) {
                float2 h2 = *(const float2*)(hrow + j * TILE_E);
                u64 h0 = pack2(h2.x, h2.x);
                u64 h1 = pack2(h2.y, h2.y);
                const float* wj = wrow + j * (PP * FF);
#pragma unroll
                for (int p = 0; p < 5; p++) {
                    ulonglong2 w = *(const ulonglong2*)(wj + p * FF);
                    ffma2(acc[0][p][0], w.x, h0);
                    ffma2(acc[0][p][1], w.y, h0);
                    ffma2(acc[1][p][0], w.x, h1);
                    ffma2(acc[1][p][1], w.y, h1);
                }
            }
        }

        // ---- phase C: CG tensor product + vector scatter ----
#pragma unroll
        for (int e2 = 0; e2 < 2; e2++) {
            int le = eg * 2 + e2;
            int snd = sSnd[le], rcv = sRcv[le];
            float Yx = sY[le * 3 + 0], Yy = sY[le * 3 + 1], Yz = sY[le * 3 + 2];
            float4 ss = *(const float4*)(g_s1 + snd * FF + fg * 4);
            const float* vp = g_v1 + snd * FF * 3 + fg * 12;
            float4 va = *(const float4*)(vp);
            float4 vb = *(const float4*)(vp + 4);
            float4 vc = *(const float4*)(vp + 8);

            float tw[5][4];
#pragma unroll
            for (int p = 0; p < 5; p++) {
                float2 a = unpk(acc[e2][p][0]);
                float2 b = unpk(acc[e2][p][1]);
                tw[p][0] = a.x; tw[p][1] = a.y; tw[p][2] = b.x; tw[p][3] = b.y;
            }
            float ssf[4] = {ss.x, ss.y, ss.z, ss.w};
            float vx[4] = {va.x, va.w, vb.z, vc.y};
            float vy[4] = {va.y, vb.x, vb.w, vc.z};
            float vz[4] = {va.z, vb.y, vc.x, vc.w};
            float ms[4], mvx[4], mvy[4], mvz[4];
#pragma unroll
            for (int f = 0; f < 4; f++) {
                float dot = vx[f] * Yx + vy[f] * Yy + vz[f] * Yz;
                float cx = vy[f] * Yz - vz[f] * Yy;
                float cy = vz[f] * Yx - vx[f] * Yz;
                float cz = vx[f] * Yy - vy[f] * Yx;
                ms[f] = tw[0][f] * ssf[f] + tw[1][f] * dot * INV_SQRT3;
                float t2s = tw[2][f] * ssf[f];
                float t4 = tw[4][f] * INV_SQRT2;
                mvx[f] = t2s * Yx + tw[3][f] * vx[f] + t4 * cx;
                mvy[f] = t2s * Yy + tw[3][f] * vy[f] + t4 * cy;
                mvz[f] = t2s * Yz + tw[3][f] * vz[f] + t4 * cz;
            }
            red4(g_As + rcv * FF + fg * 4, ms[0], ms[1], ms[2], ms[3]);
            float* avp = g_Av + rcv * FF * 3 + fg * 12;
            red4(avp + 0, mvx[0], mvy[0], mvz[0], mvx[1]);
            red4(avp + 4, mvy[1], mvz[1], mvx[2], mvy[2]);
            red4(avp + 8, mvz[2], mvx[3], mvy[3], mvz[3]);
        }
    }
}

// ---------------------------------------------------------------------------
// Kernel C: node post: W_int + species skip + product basis + W_prod + readout
// ---------------------------------------------------------------------------
__global__ __launch_bounds__(256, 2) void knodeC(
    const float* __restrict__ s, const float* __restrict__ v,
    const int* __restrict__ spec,
    const float* __restrict__ W_sc_s, const float* __restrict__ W_sc_v,
    const float* __restrict__ W_int_s, const float* __restrict__ W_int_v,
    const float* __restrict__ w_prod_s, const float* __restrict__ w_prod_v,
    const float* __restrict__ W_prod_s, const float* __restrict__ W_prod_v,
    const float* __restrict__ W_read,
    float* __restrict__ out_node, float* __restrict__ out_s,
    float* __restrict__ out_v)
{
    extern __shared__ float sm[];
    float* sWis = sm;
    float* sWiv = sWis + FF * FF;
    float* sWps = sWiv + FF * FF;
    float* sWpv = sWps + FF * FF;
    float* sWr  = sWpv + FF * FF;
    float* sAs  = sWr + FF;
    float* sAv  = sAs + 4 * FF;
    float* sSin = sAv + 4 * FF * 3;
    float* sVin = sSin + 4 * FF;
    float* sBs  = sVin + 4 * FF * 3;
    float* sBv  = sBs + 4 * FF;
    float* sRed = sBv + 4 * FF * 3;
    __shared__ int sSpec[4];

    for (int i = threadIdx.x; i < FF * FF; i += blockDim.x) {
        sWis[i] = W_int_s[i];
        sWiv[i] = W_int_v[i];
        sWps[i] = W_prod_s[i];
        sWpv[i] = W_prod_v[i];
    }
    if (threadIdx.x < FF) sWr[threadIdx.x] = W_read[threadIdx.x];

    const int ngrp = NN / 4;
    for (int grp = blockIdx.x; grp < ngrp; grp += gridDim.x) {
        __syncthreads();
        int nbase = grp * 4;
        for (int i = threadIdx.x; i < 4 * FF; i += blockDim.x) {
            sAs[i] = g_As[nbase * FF + i];
            sSin[i] = s[nbase * FF + i];
        }
        for (int i = threadIdx.x; i < 4 * FF * 3; i += blockDim.x) {
            sAv[i] = g_Av[nbase * FF * 3 + i];
            sVin[i] = v[nbase * FF * 3 + i];
        }
        if (threadIdx.x < 4) sSpec[threadIdx.x] = spec[nbase + threadIdx.x];
        __syncthreads();

        int nl = threadIdx.x >> 6, g = threadIdx.x & 63;
        int n = nbase + nl;
        int sp = sSpec[nl];
        const float* Wscs = W_sc_s + sp * FF * FF;
        const float* Wscv = W_sc_v + sp * FF * FF;
        const float* pAs = sAs + nl * FF;
        const float* pAv = sAv + nl * FF * 3;
        const float* pS = sSin + nl * FF;
        const float* pV = sVin + nl * FF * 3;

        float as = 0.f, avx = 0.f, avy = 0.f, avz = 0.f;
        float scs = 0.f, scvx = 0.f, scvy = 0.f, scvz = 0.f;
#pragma unroll 4
        for (int f = 0; f < FF; f++) {
            float wis = sWis[f * FF + g], wiv = sWiv[f * FF + g];
            float wss = __ldg(Wscs + f * FF + g);
            float wsv = __ldg(Wscv + f * FF + g);
            as += pAs[f] * wis;
            avx += pAv[f * 3 + 0] * wiv;
            avy += pAv[f * 3 + 1] * wiv;
            avz += pAv[f * 3 + 2] * wiv;
            scs += pS[f] * wss;
            scvx += pV[f * 3 + 0] * wsv;
            scvy += pV[f * 3 + 1] * wsv;
            scvz += pV[f * 3 + 2] * wsv;
        }
        const float inv = 0.25f;
        as *= inv; avx *= inv; avy *= inv; avz *= inv;

        const float* wps = w_prod_s + sp * 5 * FF;
        const float* wpv = w_prod_v + sp * 4 * FF;
        float d = avx * avx + avy * avy + avz * avz;
        float as2 = as * as;
        float Bs = wps[0 * FF + g] * as + wps[1 * FF + g] * as2 +
                   wps[2 * FF + g] * d + wps[3 * FF + g] * as2 * as +
                   wps[4 * FF + g] * as * d;
        float gv = wpv[0 * FF + g] + wpv[1 * FF + g] * as +
                   wpv[2 * FF + g] * as2 + wpv[3 * FF + g] * d;
        sBs[nl * FF + g] = Bs;
        sBv[nl * FF * 3 + g * 3 + 0] = gv * avx;
        sBv[nl * FF * 3 + g * 3 + 1] = gv * avy;
        sBv[nl * FF * 3 + g * 3 + 2] = gv * avz;
        __syncthreads();

        const float* pBs = sBs + nl * FF;
        const float* pBv = sBv + nl * FF * 3;
        float so = scs, vox = scvx, voy = scvy, voz = scvz;
#pragma unroll 4
        for (int f = 0; f < FF; f++) {
            float wp = sWps[f * FF + g], wv = sWpv[f * FF + g];
            so += pBs[f] * wp;
            vox += pBv[f * 3 + 0] * wv;
            voy += pBv[f * 3 + 1] * wv;
            voz += pBv[f * 3 + 2] * wv;
        }
        out_s[n * FF + g] = so;
        out_v[n * FF * 3 + g * 3 + 0] = vox;
        out_v[n * FF * 3 + g * 3 + 1] = voy;
        out_v[n * FF * 3 + g * 3 + 2] = voz;

        float r = so * sWr[g];
#pragma unroll
        for (int o = 16; o > 0; o >>= 1) r += __shfl_down_sync(0xffffffffu, r, o);
        if ((threadIdx.x & 31) == 0) sRed[threadIdx.x >> 5] = r;
        __syncthreads();
        if ((threadIdx.x & 63) == 0)
            out_node[n] = sRed[threadIdx.x >> 5] + sRed[(threadIdx.x >> 5) + 1];
    }
}

// ---------------------------------------------------------------------------
extern "C" void kernel_launch(void* const* d_in, const int* in_sizes, int n_in,
                              void* d_out, int out_size)
{
    const float* s    = (const float*)d_in[0];
    const float* v    = (const float*)d_in[1];
    const float* Y1   = (const float*)d_in[2];
    const float* ef   = (const float*)d_in[3];
    const int*   spec = (const int*)d_in[4];
    const int*   snd  = (const int*)d_in[5];
    const int*   rcv  = (const int*)d_in[6];
    const float* Wls  = (const float*)d_in[7];
    const float* Wlv  = (const float*)d_in[8];
    const float* Wscs = (const float*)d_in[9];
    const float* Wscv = (const float*)d_in[10];
    const float* Wr1  = (const float*)d_in[11];
    const float* Wr2  = (const float*)d_in[12];
    const float* Wis  = (const float*)d_in[13];
    const float* Wiv  = (const float*)d_in[14];
    const float* wps  = (const float*)d_in[15];
    const float* wpv  = (const float*)d_in[16];
    const float* Wps  = (const float*)d_in[17];
    const float* Wpv  = (const float*)d_in[18];
    const float* Wrd  = (const float*)d_in[19];

    float* out = (float*)d_out;
    float* out_node = out;
    float* out_s = out + NN;
    float* out_v = out + NN + NN * FF;

    const int smemB = (HH * PP * FF + 512 + HH * TILE_E + 96 + 2 * TILE_E) *
                      (int)sizeof(float);  // 92928 B
    const int smemC = (4 * FF * FF + FF + 4 * FF * 2 + 4 * FF * 3 * 2 +
                       4 * FF + 4 * FF * 3 + 8) * (int)sizeof(float);
    cudaFuncSetAttribute(kedge, cudaFuncAttributeMaxDynamicSharedMemorySize, smemB);
    cudaFuncSetAttribute(knodeC, cudaFuncAttributeMaxDynamicSharedMemorySize, smemC);

    knodeA<<<592, 256>>>(s, v, Wls, Wlv);
    kedge<<<296, 256, smemB>>>(Y1, ef, snd, rcv, Wr1, Wr2);
    knodeC<<<296, 256, smemC>>>(s, v, spec, Wscs, Wscv, Wis, Wiv,
                                wps, wpv, Wps, Wpv, Wrd,
                                out_node, out_s, out_v);
}